// round 1
// baseline (speedup 1.0000x reference)
#include <cuda_runtime.h>

// DepthAwareTokenAggregator: B=8, N=512, Y=64, C=256
// Inputs (metadata order): sampled[B,N,Y,C] f32, valid[B,N,Y] f32, y_norm[Y] f32,
//                          W1[C+1,C] f32, b1[C] f32, W2[C,1] f32, b2[1] f32
// Output: [B,N,C] f32
//
// One CTA per token (bn). 256 threads = 8 warps.
// Thread (ty=warp 0..7, tx=lane 0..31) computes an 8(y) x 8(j) tile of
// pre = feat @ W1, with j = tx + 32*jj (conflict-free SMEM, coalesced GMEM).
// Inner product uses packed fma.rn.f32x2 (2 fp32 FMA / instr).

#define TOKENS 4096
#define Yd 64
#define Cd 256
#define KC 32          // W1 k-chunk rows staged in SMEM
#define THREADS 256

__device__ __forceinline__ float gelu_exact(float x) {
    return 0.5f * x * (1.0f + erff(x * 0.70710678118654752440f));
}

#define FMA2(d, a, b) asm("fma.rn.f32x2 %0, %1, %2, %0;" : "+l"(d) : "l"(a), "l"(b))

__device__ __forceinline__ unsigned long long pack2(float lo, float hi) {
    unsigned long long r;
    asm("mov.b64 %0, {%1, %2};" : "=l"(r) : "r"(__float_as_uint(lo)), "r"(__float_as_uint(hi)));
    return r;
}
__device__ __forceinline__ void unpack2(unsigned long long v, float& lo, float& hi) {
    unsigned int l, h;
    asm("mov.b64 {%0, %1}, %2;" : "=r"(l), "=r"(h) : "l"(v));
    lo = __uint_as_float(l);
    hi = __uint_as_float(h);
}

__global__ __launch_bounds__(THREADS, 2)
void dat_kernel(const float* __restrict__ sampled,
                const float* __restrict__ valid,
                const float* __restrict__ y_norm,
                const float* __restrict__ W1,
                const float* __restrict__ b1,
                const float* __restrict__ W2,
                const float* __restrict__ b2,
                float* __restrict__ out)
{
    extern __shared__ float smem[];
    float* feat_s   = smem;                  // [64][256] sampled tile
    float* w1_s     = feat_s + Yd * Cd;      // [KC][256] W1 chunk
    float* logits_s = w1_s + KC * Cd;        // [64]
    float* wgt_s    = logits_s + Yd;         // [64]

    const int bn  = blockIdx.x;
    const int tid = threadIdx.x;
    const int ty  = tid >> 5;   // warp id -> y block (8 rows each)
    const int tx  = tid & 31;   // lane    -> j base

    // ---- Load sampled tile (64x256 f32 = 64KB) into SMEM, flat float4 copy ----
    {
        const float4* src4 = reinterpret_cast<const float4*>(sampled + (size_t)bn * (Yd * Cd));
        float4* dst4 = reinterpret_cast<float4*>(feat_s);
        #pragma unroll
        for (int r = 0; r < 16; r++)
            dst4[tid + r * THREADS] = src4[tid + r * THREADS];
    }

    // ---- Per-thread constants: y_norm for my 8 rows; W1 last row / b1 / W2 for my 8 cols ----
    float yn[8];
    #pragma unroll
    for (int i = 0; i < 8; i++) yn[i] = __ldg(&y_norm[ty * 8 + i]);

    float w1l[8], b1v[8], w2v[8];
    #pragma unroll
    for (int jj = 0; jj < 8; jj++) {
        int j = tx + 32 * jj;
        w1l[jj] = __ldg(&W1[(size_t)Cd * Cd + j]);   // W1[256, j] (y_norm feature row)
        b1v[jj] = __ldg(&b1[j]);
        w2v[jj] = __ldg(&W2[j]);
    }

    // ---- Accumulators: 8 y x 8 j as 8x4 packed f32x2 (lo = jj even, hi = jj odd) ----
    unsigned long long acc[8][4];
    #pragma unroll
    for (int i = 0; i < 8; i++)
        #pragma unroll
        for (int q = 0; q < 4; q++) acc[i][q] = 0ull;

    // ---- Main GEMM: k = 0..255 in 8 chunks of 32, W1 chunk staged in SMEM ----
    for (int kc = 0; kc < 8; kc++) {
        __syncthreads();  // protect w1_s reuse (and feat_s fill on first iter)
        {
            const float4* wsrc = reinterpret_cast<const float4*>(W1 + (size_t)kc * KC * Cd);
            float4* wdst = reinterpret_cast<float4*>(w1_s);
            #pragma unroll
            for (int r = 0; r < 8; r++)
                wdst[tid + r * THREADS] = wsrc[tid + r * THREADS];
        }
        __syncthreads();

        #pragma unroll 2
        for (int kk = 0; kk < KC; kk++) {
            const int k = kc * KC + kk;
            // b: 8 scalar conflict-free LDS (lanes consecutive), pack to f32x2
            float bf[8];
            #pragma unroll
            for (int jj = 0; jj < 8; jj++)
                bf[jj] = w1_s[kk * Cd + tx + 32 * jj];
            unsigned long long b2p[4];
            #pragma unroll
            for (int q = 0; q < 4; q++) b2p[q] = pack2(bf[2 * q], bf[2 * q + 1]);

            #pragma unroll
            for (int i = 0; i < 8; i++) {
                float a = feat_s[(ty * 8 + i) * Cd + k];  // warp-broadcast
                unsigned long long a2;
                asm("mov.b64 %0, {%1, %1};" : "=l"(a2) : "r"(__float_as_uint(a)));
                FMA2(acc[i][0], a2, b2p[0]);
                FMA2(acc[i][1], a2, b2p[1]);
                FMA2(acc[i][2], a2, b2p[2]);
                FMA2(acc[i][3], a2, b2p[3]);
            }
        }
    }

    // ---- Epilogue: add y_norm feature term + bias, gelu, dot with W2 -> logit partials ----
    float partial[8];
    #pragma unroll
    for (int i = 0; i < 8; i++) {
        float p = 0.0f;
        #pragma unroll
        for (int q = 0; q < 4; q++) {
            float x0, x1;
            unpack2(acc[i][q], x0, x1);
            x0 = x0 + yn[i] * w1l[2 * q]     + b1v[2 * q];
            x1 = x1 + yn[i] * w1l[2 * q + 1] + b1v[2 * q + 1];
            p += gelu_exact(x0) * w2v[2 * q] + gelu_exact(x1) * w2v[2 * q + 1];
        }
        partial[i] = p;
    }

    // ---- Reduce logits across lanes (j dimension), lane 0 writes ----
    const float b2val = __ldg(b2);
    #pragma unroll
    for (int i = 0; i < 8; i++) {
        float p = partial[i];
        #pragma unroll
        for (int off = 16; off > 0; off >>= 1)
            p += __shfl_xor_sync(0xffffffffu, p, off);
        if (tx == 0) logits_s[ty * 8 + i] = p + b2val;
    }
    __syncthreads();

    // ---- Masked softmax over Y=64 (warp 0, 2 values/lane) ----
    if (tid < 32) {
        const int y0 = tid, y1 = tid + 32;
        const float v0 = valid[(size_t)bn * Yd + y0];
        const float v1 = valid[(size_t)bn * Yd + y1];
        float l0 = (v0 < 0.5f) ? -10000.0f : logits_s[y0];
        float l1 = (v1 < 0.5f) ? -10000.0f : logits_s[y1];

        float m = fmaxf(l0, l1);
        #pragma unroll
        for (int off = 16; off > 0; off >>= 1)
            m = fmaxf(m, __shfl_xor_sync(0xffffffffu, m, off));

        float e0 = expf(l0 - m), e1 = expf(l1 - m);
        float s = e0 + e1;
        #pragma unroll
        for (int off = 16; off > 0; off >>= 1)
            s += __shfl_xor_sync(0xffffffffu, s, off);

        float p0 = (e0 / s) * v0;
        float p1 = (e1 / s) * v1;
        float s2 = p0 + p1;
        #pragma unroll
        for (int off = 16; off > 0; off >>= 1)
            s2 += __shfl_xor_sync(0xffffffffu, s2, off);

        const float inv = 1.0f / fmaxf(s2, 1e-6f);
        wgt_s[y0] = p0 * inv;
        wgt_s[y1] = p1 * inv;
    }
    __syncthreads();

    // ---- Weighted aggregation: out[c] = sum_y sampled[y,c] * w[y] (from SMEM tile) ----
    {
        float o = 0.0f;
        #pragma unroll
        for (int y = 0; y < Yd; y++)
            o = fmaf(feat_s[y * Cd + tid], wgt_s[y], o);
        out[(size_t)bn * Cd + tid] = o;
    }
}

extern "C" void kernel_launch(void* const* d_in, const int* in_sizes, int n_in,
                              void* d_out, int out_size)
{
    const float* sampled = (const float*)d_in[0];
    const float* valid   = (const float*)d_in[1];
    const float* y_norm  = (const float*)d_in[2];
    const float* W1      = (const float*)d_in[3];
    const float* b1      = (const float*)d_in[4];
    const float* W2      = (const float*)d_in[5];
    const float* b2      = (const float*)d_in[6];
    float* out = (float*)d_out;

    const int smem_bytes = (Yd * Cd + KC * Cd + 2 * Yd) * (int)sizeof(float);  // ~96.5 KB
    cudaFuncSetAttribute(dat_kernel, cudaFuncAttributeMaxDynamicSharedMemorySize, smem_bytes);
    dat_kernel<<<TOKENS, THREADS, smem_bytes>>>(sampled, valid, y_norm, W1, b1, W2, b2, out);
}

// round 5
// speedup vs baseline: 1.9412x; 1.9412x over previous
#include <cuda_runtime.h>
#include <cuda_bf16.h>
#include <cstdint>

// DepthAwareTokenAggregator via mma.sync bf16 (sm_80 ISA, no arch-suffix features).
// B=8, N=512, Y=64, C=256. 2 tokens/CTA: M=128 rows, K=256, N=256 (2 passes of 128).
// Split-bf16 hi/lo, 3 products -> ~1e-5 rel err.

#define Yd 64
#define Cd 256
#define THREADS 512
#define CTAS 2048

// ---- smem byte offsets ----
#define SM_YN    0        // 64 f32
#define SM_B1    256      // 256 f32
#define SM_W2    1280     // 256 f32
#define SM_W1L   2304     // 256 f32 (W1 row 256: y_norm feature row)
#define SM_LP    3328     // 4 x 128 f32 logit partials (per wn)
#define SM_LOG   5376     // 128 f32 logits
#define SM_WGT   5888     // 128 f32 softmax weights
#define SM_AH    6400     // 128 rows x 264 bf16 (stride 528B)
#define SM_AL    73984
#define SM_B0H   141568   // B chunk bufs: [128 n][72 k] bf16 (stride 144B), 18432B each
#define SMEM_TOTAL 215296

#define A_STRIDE 528      // bytes per A row (264 bf16)
#define B_STRIDE 144      // bytes per B row (72 bf16)
#define BBUF_SZ  18432

static __device__ __forceinline__ uint32_t smem_u32(const void* p) {
    uint32_t a;
    asm("{ .reg .u64 t; cvta.to.shared.u64 t, %1; cvt.u32.u64 %0, t; }" : "=r"(a) : "l"(p));
    return a;
}

static __device__ __forceinline__ void ldsm4(uint32_t* r, uint32_t addr) {
    asm volatile("ldmatrix.sync.aligned.m8n8.x4.shared.b16 {%0,%1,%2,%3}, [%4];"
                 : "=r"(r[0]), "=r"(r[1]), "=r"(r[2]), "=r"(r[3]) : "r"(addr));
}

static __device__ __forceinline__ void mma16816(float* d, const uint32_t* a,
                                                uint32_t b0, uint32_t b1) {
    asm volatile(
        "mma.sync.aligned.m16n8k16.row.col.f32.bf16.bf16.f32 "
        "{%0,%1,%2,%3}, {%4,%5,%6,%7}, {%8,%9}, {%0,%1,%2,%3};"
        : "+f"(d[0]), "+f"(d[1]), "+f"(d[2]), "+f"(d[3])
        : "r"(a[0]), "r"(a[1]), "r"(a[2]), "r"(a[3]), "r"(b0), "r"(b1));
}

// fp32 pair -> packed bf16x2 hi and lo (a in low half)
static __device__ __forceinline__ uint32_t split2(float a, float b, uint32_t& lo2) {
    __nv_bfloat16 ha = __float2bfloat16(a);
    __nv_bfloat16 hb = __float2bfloat16(b);
    __nv_bfloat16 la = __float2bfloat16(a - __bfloat162float(ha));
    __nv_bfloat16 lb = __float2bfloat16(b - __bfloat162float(hb));
    lo2 = (uint32_t)__bfloat16_as_ushort(la) | ((uint32_t)__bfloat16_as_ushort(lb) << 16);
    return (uint32_t)__bfloat16_as_ushort(ha) | ((uint32_t)__bfloat16_as_ushort(hb) << 16);
}

static __device__ __forceinline__ float gelu_exact(float x) {
    return 0.5f * x * (1.0f + erff(x * 0.70710678118654752440f));
}

__global__ __launch_bounds__(THREADS, 1)
void dat_mma_kernel(const float* __restrict__ sampled,
                    const float* __restrict__ valid,
                    const float* __restrict__ y_norm,
                    const float* __restrict__ W1,
                    const float* __restrict__ b1,
                    const float* __restrict__ W2,
                    const float* __restrict__ b2,
                    float* __restrict__ out)
{
    extern __shared__ char smem[];
    const uint32_t sbase = smem_u32(smem);
    const int tid  = threadIdx.x;
    const int wid  = tid >> 5;
    const int lane = tid & 31;
    const int bn2  = blockIdx.x;

    // warp tile: wm in [0,4) -> m0, wn in [0,4) -> n (within 128-col pass)
    const int wm = wid & 3, wn = wid >> 2;
    const int m0 = wm * 32, n0w = wn * 32;

    // ---- small vectors ----
    if (tid < Yd) ((float*)(smem + SM_YN))[tid] = y_norm[tid];
    if (tid < Cd) {
        ((float*)(smem + SM_B1))[tid]  = b1[tid];
        ((float*)(smem + SM_W2))[tid]  = W2[tid];
        ((float*)(smem + SM_W1L))[tid] = W1[(size_t)Cd * Cd + tid];
    }

    // ---- A: 128 rows x 256 f32 -> bf16 hi/lo, padded row-major ----
    {
        const float4* src = (const float4*)(sampled + (size_t)bn2 * (2 * Yd * Cd));
        #pragma unroll
        for (int i = 0; i < 16; i++) {
            int idx4 = tid + i * THREADS;          // 0..8191
            float4 v = src[idx4];
            int row = idx4 >> 6;                   // 0..127
            int c4  = (idx4 & 63) << 2;            // 0..252
            uint32_t lo01, lo23;
            uint32_t hi01 = split2(v.x, v.y, lo01);
            uint32_t hi23 = split2(v.z, v.w, lo23);
            uint32_t byo = row * A_STRIDE + c4 * 2;
            *(uint2*)(smem + SM_AH + byo) = make_uint2(hi01, hi23);
            *(uint2*)(smem + SM_AL + byo) = make_uint2(lo01, lo23);
        }
    }

    float lp[4] = {0.f, 0.f, 0.f, 0.f};           // logit partials, persist over passes

    const int bn = tid & 127;                      // B-load: n within pass half
    const int ks = (tid >> 7) * 16;                // k sub-range 0/16/32/48

    #pragma unroll
    for (int p = 0; p < 2; p++) {
        float acc[2][4][4];
        #pragma unroll
        for (int mt = 0; mt < 2; mt++)
            #pragma unroll
            for (int nt = 0; nt < 4; nt++)
                #pragma unroll
                for (int e = 0; e < 4; e++) acc[mt][nt][e] = 0.f;

        // prologue LDG chunk 0
        float r[16];
        #pragma unroll
        for (int j = 0; j < 16; j++)
            r[j] = W1[(size_t)(ks + j) * Cd + p * 128 + bn];

        for (int c = 0; c < 4; c++) {
            const uint32_t bufH = sbase + SM_B0H + (c & 1) * 2 * BBUF_SZ;
            const uint32_t bufL = bufH + BBUF_SZ;
            // STS chunk c (hi/lo, 8 words each = 2 x STS.128)
            {
                uint32_t h[8], l[8];
                #pragma unroll
                for (int j = 0; j < 8; j++)
                    h[j] = split2(r[2 * j], r[2 * j + 1], l[j]);
                uint32_t byo = bn * B_STRIDE + ks * 2;
                *(uint4*)(smem + (bufH - sbase) + byo)      = make_uint4(h[0], h[1], h[2], h[3]);
                *(uint4*)(smem + (bufH - sbase) + byo + 16) = make_uint4(h[4], h[5], h[6], h[7]);
                *(uint4*)(smem + (bufL - sbase) + byo)      = make_uint4(l[0], l[1], l[2], l[3]);
                *(uint4*)(smem + (bufL - sbase) + byo + 16) = make_uint4(l[4], l[5], l[6], l[7]);
            }
            __syncthreads();
            // LDG chunk c+1
            if (c < 3) {
                int k0n = (c + 1) * 64;
                #pragma unroll
                for (int j = 0; j < 16; j++)
                    r[j] = W1[(size_t)(k0n + ks + j) * Cd + p * 128 + bn];
            }
            // MMA over chunk c: 4 k16-steps
            #pragma unroll
            for (int kk = 0; kk < 4; kk++) {
                const int kglob = c * 64 + kk * 16;
                uint32_t ah[2][4], al[2][4], bh[2][4], bl[2][4];
                {
                    uint32_t abase = (uint32_t)((m0 + (lane & 15)) * A_STRIDE
                                     + (kglob + ((lane & 16) >> 1)) * 2);
                    ldsm4(ah[0], sbase + SM_AH + abase);
                    ldsm4(ah[1], sbase + SM_AH + abase + 16 * A_STRIDE);
                    ldsm4(al[0], sbase + SM_AL + abase);
                    ldsm4(al[1], sbase + SM_AL + abase + 16 * A_STRIDE);
                }
                {
                    uint32_t bbase = (uint32_t)((n0w + (lane & 7) + ((lane & 16) >> 1)) * B_STRIDE
                                     + (kk * 16 + (lane & 8)) * 2);
                    ldsm4(bh[0], bufH + bbase);
                    ldsm4(bh[1], bufH + bbase + 16 * B_STRIDE);
                    ldsm4(bl[0], bufL + bbase);
                    ldsm4(bl[1], bufL + bbase + 16 * B_STRIDE);
                }
                #pragma unroll
                for (int mt = 0; mt < 2; mt++)
                    #pragma unroll
                    for (int q = 0; q < 2; q++)
                        #pragma unroll
                        for (int h = 0; h < 2; h++) {
                            float* d = acc[mt][q * 2 + h];
                            mma16816(d, ah[mt], bh[q][2 * h], bh[q][2 * h + 1]);
                            mma16816(d, al[mt], bh[q][2 * h], bh[q][2 * h + 1]);
                            mma16816(d, ah[mt], bl[q][2 * h], bl[q][2 * h + 1]);
                        }
            }
            __syncthreads();
        }

        // ---- epilogue of pass p: gelu + dot W2 into lp ----
        {
            const float* b1s  = (const float*)(smem + SM_B1);
            const float* w2s  = (const float*)(smem + SM_W2);
            const float* w1ls = (const float*)(smem + SM_W1L);
            const float* yns  = (const float*)(smem + SM_YN);
            float yl[8], bb[8], ww[8];
            #pragma unroll
            for (int nt = 0; nt < 4; nt++)
                #pragma unroll
                for (int eb = 0; eb < 2; eb++) {
                    int n = p * 128 + n0w + nt * 8 + 2 * (lane & 3) + eb;
                    yl[nt * 2 + eb] = w1ls[n];
                    bb[nt * 2 + eb] = b1s[n];
                    ww[nt * 2 + eb] = w2s[n];
                }
            #pragma unroll
            for (int mt = 0; mt < 2; mt++)
                #pragma unroll
                for (int h = 0; h < 2; h++) {
                    int row = m0 + mt * 16 + (lane >> 2) + h * 8;
                    float yn = yns[row & 63];
                    float s = 0.f;
                    #pragma unroll
                    for (int nt = 0; nt < 4; nt++)
                        #pragma unroll
                        for (int eb = 0; eb < 2; eb++) {
                            float x = acc[mt][nt][h * 2 + eb]
                                      + yn * yl[nt * 2 + eb] + bb[nt * 2 + eb];
                            s += gelu_exact(x) * ww[nt * 2 + eb];
                        }
                    lp[mt * 2 + h] += s;
                }
        }
    }

    // ---- reduce logits: lanes sharing a row (lane&3 group), then across wn ----
    #pragma unroll
    for (int i = 0; i < 4; i++) {
        lp[i] += __shfl_xor_sync(0xffffffffu, lp[i], 1);
        lp[i] += __shfl_xor_sync(0xffffffffu, lp[i], 2);
    }
    if ((lane & 3) == 0) {
        #pragma unroll
        for (int mt = 0; mt < 2; mt++)
            #pragma unroll
            for (int h = 0; h < 2; h++) {
                int row = m0 + mt * 16 + (lane >> 2) + h * 8;
                ((float*)(smem + SM_LP))[wn * 128 + row] = lp[mt * 2 + h];
            }
    }
    __syncthreads();

    if (tid < 128) {
        const float* lps = (const float*)(smem + SM_LP);
        ((float*)(smem + SM_LOG))[tid] =
            lps[tid] + lps[128 + tid] + lps[256 + tid] + lps[384 + tid] + __ldg(b2);
    }
    __syncthreads();

    // ---- masked softmax: warp 0 -> token 0, warp 1 -> token 1 ----
    if (wid < 2) {
        const int tk = wid;
        const float* logit = (const float*)(smem + SM_LOG);
        const float v0 = valid[(size_t)(bn2 * 2 + tk) * Yd + lane];
        const float v1 = valid[(size_t)(bn2 * 2 + tk) * Yd + lane + 32];
        float l0 = (v0 < 0.5f) ? -10000.0f : logit[tk * 64 + lane];
        float l1 = (v1 < 0.5f) ? -10000.0f : logit[tk * 64 + lane + 32];

        float m = fmaxf(l0, l1);
        #pragma unroll
        for (int off = 16; off > 0; off >>= 1)
            m = fmaxf(m, __shfl_xor_sync(0xffffffffu, m, off));
        float e0 = expf(l0 - m), e1 = expf(l1 - m);
        float s = e0 + e1;
        #pragma unroll
        for (int off = 16; off > 0; off >>= 1)
            s += __shfl_xor_sync(0xffffffffu, s, off);
        float p0 = (e0 / s) * v0;
        float p1 = (e1 / s) * v1;
        float s2 = p0 + p1;
        #pragma unroll
        for (int off = 16; off > 0; off >>= 1)
            s2 += __shfl_xor_sync(0xffffffffu, s2, off);
        const float inv = 1.0f / fmaxf(s2, 1e-6f);
        ((float*)(smem + SM_WGT))[tk * 64 + lane]      = p0 * inv;
        ((float*)(smem + SM_WGT))[tk * 64 + lane + 32] = p1 * inv;
    }
    __syncthreads();

    // ---- aggregation: out[t][c] = sum_y w[row] * (Ah+Al)[row][c] ----
    {
        const float* wgt = (const float*)(smem + SM_WGT);
        const int t = tid >> 8, c = tid & 255;
        float o = 0.f;
        #pragma unroll 16
        for (int y = 0; y < 64; y++) {
            int row = t * 64 + y;
            uint32_t byo = row * A_STRIDE + c * 2;
            float h = __bfloat162float(*(const __nv_bfloat16*)(smem + SM_AH + byo));
            float l = __bfloat162float(*(const __nv_bfloat16*)(smem + SM_AL + byo));
            o = fmaf(wgt[row], h + l, o);
        }
        out[(size_t)(bn2 * 2 + t) * Cd + c] = o;
    }
}

extern "C" void kernel_launch(void* const* d_in, const int* in_sizes, int n_in,
                              void* d_out, int out_size)
{
    const float* sampled = (const float*)d_in[0];
    const float* valid   = (const float*)d_in[1];
    const float* y_norm  = (const float*)d_in[2];
    const float* W1      = (const float*)d_in[3];
    const float* b1      = (const float*)d_in[4];
    const float* W2      = (const float*)d_in[5];
    const float* b2      = (const float*)d_in[6];
    float* out = (float*)d_out;

    cudaFuncSetAttribute(dat_mma_kernel, cudaFuncAttributeMaxDynamicSharedMemorySize, SMEM_TOTAL);
    dat_mma_kernel<<<CTAS, THREADS, SMEM_TOTAL>>>(sampled, valid, y_norm, W1, b1, W2, b2, out);
}

// round 7
// speedup vs baseline: 2.9717x; 1.5309x over previous
#include <cuda_runtime.h>
#include <cuda_fp16.h>
#include <cstdint>

// DepthAwareTokenAggregator via mma.sync fp16 (sm_80 ISA).
// B=8, N=512, Y=64, C=256. 2 tokens/CTA: M=128, K=256, N=256 (2 passes of 128).
// W1 prepacked (fp16 hi+lo) once by a pre-kernel; streamed via cp.async.
// 2-product split: A_fp16 * (W1h + W1l)  ->  rel err ~ eps_fp16/sqrt(3) ~ 3e-4.

#define Yd 64
#define Cd 256
#define THREADS 256
#define CTAS 2048

// ---- smem byte offsets ----
#define SM_YN    0        // 64 f32
#define SM_B1    256      // 256 f32
#define SM_W2    1280     // 256 f32
#define SM_W1L   2304     // 256 f32 (W1 row 256: y_norm feature row)
#define SM_LP    3328     // 4 x 128 f32 logit partials
#define SM_LOG   5376     // 128 f32
#define SM_WGT   5888     // 128 f32
#define SM_A     6400     // 128 rows x 264 fp16 (stride 528B) = 67584
#define SM_B     73984    // 2 bufs x (hi 10240 + lo 10240) = 40960
#define SMEM_TOTAL 114944

#define A_STRIDE 528
#define B_STRIDE 80       // 32 fp16 (64B) + 16B pad
#define BCHUNK   20480    // one buffer: hi + lo

// prepacked W1: [16 chunks][2 hl][128 n][32 k] fp16  (chunk = pass*8 + kc)
__device__ __half w1pack[16 * 2 * 128 * 32];

static __device__ __forceinline__ uint32_t smem_u32(const void* p) {
    uint32_t a;
    asm("{ .reg .u64 t; cvta.to.shared.u64 t, %1; cvt.u32.u64 %0, t; }" : "=r"(a) : "l"(p));
    return a;
}

static __device__ __forceinline__ void ldsm4(uint32_t* r, uint32_t addr) {
    asm volatile("ldmatrix.sync.aligned.m8n8.x4.shared.b16 {%0,%1,%2,%3}, [%4];"
                 : "=r"(r[0]), "=r"(r[1]), "=r"(r[2]), "=r"(r[3]) : "r"(addr));
}

static __device__ __forceinline__ void mma16816(float* d, const uint32_t* a,
                                                uint32_t b0, uint32_t b1) {
    asm volatile(
        "mma.sync.aligned.m16n8k16.row.col.f32.f16.f16.f32 "
        "{%0,%1,%2,%3}, {%4,%5,%6,%7}, {%8,%9}, {%0,%1,%2,%3};"
        : "+f"(d[0]), "+f"(d[1]), "+f"(d[2]), "+f"(d[3])
        : "r"(a[0]), "r"(a[1]), "r"(a[2]), "r"(a[3]), "r"(b0), "r"(b1));
}

#define CP_ASYNC16(dst, src) \
    asm volatile("cp.async.cg.shared.global [%0], [%1], 16;" :: "r"(dst), "l"(src) : "memory")
#define CP_COMMIT() asm volatile("cp.async.commit_group;" ::: "memory")
#define CP_WAIT1()  asm volatile("cp.async.wait_group 1;" ::: "memory")
#define CP_WAIT0()  asm volatile("cp.async.wait_group 0;" ::: "memory")

static __device__ __forceinline__ float gelu_exact(float x) {
    return 0.5f * x * (1.0f + erff(x * 0.70710678118654752440f));
}

// ---- pre-kernel: pack W1 (f32 [257,256]) -> fp16 hi/lo chunk blocks ----
__global__ void pack_w1_kernel(const float* __restrict__ W1) {
    int gid = blockIdx.x * blockDim.x + threadIdx.x;   // 0..16383
    #pragma unroll
    for (int it = 0; it < 4; it++) {
        int e = gid + it * 16384;                      // 0..65535
        int p = e >> 15;
        int rem = e & 32767;
        int k = rem >> 7;                              // 0..255
        int n = rem & 127;
        int c = k >> 5, kk = k & 31;
        float x = W1[(size_t)k * Cd + p * 128 + n];
        __half h = __float2half_rn(x);
        __half l = __float2half_rn(x - __half2float(h));
        int base = ((p * 8 + c) * 2) * 4096 + n * 32 + kk;
        w1pack[base] = h;
        w1pack[base + 4096] = l;
    }
}

static __device__ __forceinline__ void issue_chunk(uint32_t sbase, int tid, int i) {
    const uint32_t dstb = sbase + SM_B + (i & 1) * BCHUNK;
    const __half* srcb = w1pack + (size_t)i * 8192;
    #pragma unroll
    for (int hl = 0; hl < 2; hl++) {
        #pragma unroll
        for (int j = 0; j < 2; j++) {
            int idx16 = tid * 2 + j;                   // 0..511
            int n = idx16 >> 2, ko = idx16 & 3;
            uint32_t dst = dstb + hl * 10240 + n * B_STRIDE + ko * 16;
            const void* src = srcb + hl * 4096 + idx16 * 8;
            CP_ASYNC16(dst, src);
        }
    }
}

static __device__ __forceinline__ void epilogue_pass(
    float acc[4][4][4], float* lp, int p, const char* smem, int lane, int m0, int n0w)
{
    const float* b1s  = (const float*)(smem + SM_B1);
    const float* w2s  = (const float*)(smem + SM_W2);
    const float* w1ls = (const float*)(smem + SM_W1L);
    const float* yns  = (const float*)(smem + SM_YN);
    float yl[8], bb[8], ww[8];
    #pragma unroll
    for (int nt = 0; nt < 4; nt++)
        #pragma unroll
        for (int eb = 0; eb < 2; eb++) {
            int n = p * 128 + n0w + nt * 8 + 2 * (lane & 3) + eb;
            yl[nt * 2 + eb] = w1ls[n];
            bb[nt * 2 + eb] = b1s[n];
            ww[nt * 2 + eb] = w2s[n];
        }
    #pragma unroll
    for (int mt = 0; mt < 4; mt++)
        #pragma unroll
        for (int h = 0; h < 2; h++) {
            int row = m0 + mt * 16 + h * 8 + (lane >> 2);
            float yn = yns[row & 63];
            float s = 0.f;
            #pragma unroll
            for (int nt = 0; nt < 4; nt++)
                #pragma unroll
                for (int eb = 0; eb < 2; eb++) {
                    float x = acc[mt][nt][h * 2 + eb] + yn * yl[nt * 2 + eb] + bb[nt * 2 + eb];
                    s += gelu_exact(x) * ww[nt * 2 + eb];
                }
            lp[mt * 2 + h] += s;
        }
}

__global__ __launch_bounds__(THREADS, 2)
void dat_mma2_kernel(const float* __restrict__ sampled,
                     const float* __restrict__ valid,
                     const float* __restrict__ y_norm,
                     const float* __restrict__ W1,
                     const float* __restrict__ b1,
                     const float* __restrict__ W2,
                     const float* __restrict__ b2,
                     float* __restrict__ out)
{
    extern __shared__ char smem[];
    const uint32_t sbase = smem_u32(smem);
    const int tid  = threadIdx.x;
    const int wid  = tid >> 5;
    const int lane = tid & 31;
    const int bn2  = blockIdx.x;

    // warp tile: wm in {0,1} -> 64 m-rows, wn in {0..3} -> 32 n-cols
    const int wm = wid & 1, wn = wid >> 1;
    const int m0 = wm * 64, n0w = wn * 32;

    // kick off B pipeline first so it overlaps the A load/convert
    issue_chunk(sbase, tid, 0); CP_COMMIT();
    issue_chunk(sbase, tid, 1); CP_COMMIT();

    // small vectors
    if (tid < Yd) ((float*)(smem + SM_YN))[tid] = y_norm[tid];
    ((float*)(smem + SM_B1))[tid]  = b1[tid];
    ((float*)(smem + SM_W2))[tid]  = W2[tid];
    ((float*)(smem + SM_W1L))[tid] = W1[(size_t)Cd * Cd + tid];

    // ---- A: 128 rows x 256 f32 -> fp16, padded row-major ----
    {
        const float4* src = (const float4*)(sampled + (size_t)bn2 * (2 * Yd * Cd));
        #pragma unroll
        for (int i = 0; i < 32; i++) {
            int idx4 = tid + i * THREADS;          // 0..8191
            float4 v = src[idx4];
            int row = idx4 >> 6;
            int c4  = (idx4 & 63) << 2;
            __half2 h01 = __floats2half2_rn(v.x, v.y);
            __half2 h23 = __floats2half2_rn(v.z, v.w);
            uint32_t byo = row * A_STRIDE + c4 * 2;
            *(uint2*)(smem + SM_A + byo) =
                make_uint2(*(uint32_t*)&h01, *(uint32_t*)&h23);
        }
    }

    float acc[4][4][4];
    #pragma unroll
    for (int mt = 0; mt < 4; mt++)
        #pragma unroll
        for (int nt = 0; nt < 4; nt++)
            #pragma unroll
            for (int e = 0; e < 4; e++) acc[mt][nt][e] = 0.f;
    float lp[8] = {0.f, 0.f, 0.f, 0.f, 0.f, 0.f, 0.f, 0.f};

    // ---- main loop: 16 chunks (pass = i>>3, k-chunk = i&7, 32 k each) ----
    #pragma unroll 1
    for (int i = 0; i < 16; i++) {
        if (i < 15) { CP_WAIT1(); } else { CP_WAIT0(); }
        __syncthreads();

        const uint32_t bufH = sbase + SM_B + (i & 1) * BCHUNK;
        const uint32_t bufL = bufH + 10240;
        const int kbase = (i & 7) * 32;

        #pragma unroll
        for (int kk = 0; kk < 2; kk++) {
            const int kglob = kbase + kk * 16;
            uint32_t a_[4][4];
            #pragma unroll
            for (int mt = 0; mt < 4; mt++) {
                uint32_t aaddr = sbase + SM_A
                    + (uint32_t)((m0 + mt * 16 + (lane & 15)) * A_STRIDE
                                 + (kglob + ((lane & 16) >> 1)) * 2);
                ldsm4(a_[mt], aaddr);
            }
            const uint32_t bbase =
                (uint32_t)((n0w + (lane & 7) + ((lane & 16) >> 1)) * B_STRIDE
                           + (kk * 16 + (lane & 8)) * 2);
            uint32_t bf[2][4];
            ldsm4(bf[0], bufH + bbase);
            ldsm4(bf[1], bufH + bbase + 16 * B_STRIDE);
            #pragma unroll
            for (int mt = 0; mt < 4; mt++)
                #pragma unroll
                for (int q = 0; q < 2; q++)
                    #pragma unroll
                    for (int h = 0; h < 2; h++)
                        mma16816(acc[mt][q * 2 + h], a_[mt], bf[q][2 * h], bf[q][2 * h + 1]);
            ldsm4(bf[0], bufL + bbase);
            ldsm4(bf[1], bufL + bbase + 16 * B_STRIDE);
            #pragma unroll
            for (int mt = 0; mt < 4; mt++)
                #pragma unroll
                for (int q = 0; q < 2; q++)
                    #pragma unroll
                    for (int h = 0; h < 2; h++)
                        mma16816(acc[mt][q * 2 + h], a_[mt], bf[q][2 * h], bf[q][2 * h + 1]);
        }

        if (i == 7) {
            epilogue_pass(acc, lp, 0, smem, lane, m0, n0w);
            #pragma unroll
            for (int mt = 0; mt < 4; mt++)
                #pragma unroll
                for (int nt = 0; nt < 4; nt++)
                    #pragma unroll
                    for (int e = 0; e < 4; e++) acc[mt][nt][e] = 0.f;
        }
        __syncthreads();
        if (i + 2 < 16) { issue_chunk(sbase, tid, i + 2); CP_COMMIT(); }
    }
    epilogue_pass(acc, lp, 1, smem, lane, m0, n0w);

    // ---- reduce logits across the 4 lanes sharing a row, write per-wn partials ----
    #pragma unroll
    for (int i = 0; i < 8; i++) {
        lp[i] += __shfl_xor_sync(0xffffffffu, lp[i], 1);
        lp[i] += __shfl_xor_sync(0xffffffffu, lp[i], 2);
    }
    if ((lane & 3) == 0) {
        #pragma unroll
        for (int mt = 0; mt < 4; mt++)
            #pragma unroll
            for (int h = 0; h < 2; h++) {
                int row = m0 + mt * 16 + h * 8 + (lane >> 2);
                ((float*)(smem + SM_LP))[wn * 128 + row] = lp[mt * 2 + h];
            }
    }
    __syncthreads();

    if (tid < 128) {
        const float* lps = (const float*)(smem + SM_LP);
        ((float*)(smem + SM_LOG))[tid] =
            lps[tid] + lps[128 + tid] + lps[256 + tid] + lps[384 + tid] + __ldg(b2);
    }
    __syncthreads();

    // ---- masked softmax: warp 0 -> token 0, warp 1 -> token 1 ----
    if (wid < 2) {
        const int tk = wid;
        const float* logit = (const float*)(smem + SM_LOG);
        const float v0 = valid[(size_t)(bn2 * 2 + tk) * Yd + lane];
        const float v1 = valid[(size_t)(bn2 * 2 + tk) * Yd + lane + 32];
        float l0 = (v0 < 0.5f) ? -10000.0f : logit[tk * 64 + lane];
        float l1 = (v1 < 0.5f) ? -10000.0f : logit[tk * 64 + lane + 32];

        float m = fmaxf(l0, l1);
        #pragma unroll
        for (int off = 16; off > 0; off >>= 1)
            m = fmaxf(m, __shfl_xor_sync(0xffffffffu, m, off));
        float e0 = expf(l0 - m), e1 = expf(l1 - m);
        float s = e0 + e1;
        #pragma unroll
        for (int off = 16; off > 0; off >>= 1)
            s += __shfl_xor_sync(0xffffffffu, s, off);
        float p0 = (e0 / s) * v0;
        float p1 = (e1 / s) * v1;
        float s2 = p0 + p1;
        #pragma unroll
        for (int off = 16; off > 0; off >>= 1)
            s2 += __shfl_xor_sync(0xffffffffu, s2, off);
        const float inv = 1.0f / fmaxf(s2, 1e-6f);
        ((float*)(smem + SM_WGT))[tk * 64 + lane]      = p0 * inv;
        ((float*)(smem + SM_WGT))[tk * 64 + lane + 32] = p1 * inv;
    }
    __syncthreads();

    // ---- aggregation: re-read sampled f32 (L2-hot) for full output precision ----
    {
        const float* wgt = (const float*)(smem + SM_WGT);
        const int c = tid;
        #pragma unroll
        for (int t = 0; t < 2; t++) {
            const float* sp = sampled + ((size_t)(bn2 * 2 + t) * Yd) * Cd + c;
            float o = 0.f;
            #pragma unroll 8
            for (int y = 0; y < Yd; y++)
                o = fmaf(wgt[t * 64 + y], sp[(size_t)y * Cd], o);
            out[(size_t)(bn2 * 2 + t) * Cd + c] = o;
        }
    }
}

extern "C" void kernel_launch(void* const* d_in, const int* in_sizes, int n_in,
                              void* d_out, int out_size)
{
    const float* sampled = (const float*)d_in[0];
    const float* valid   = (const float*)d_in[1];
    const float* y_norm  = (const float*)d_in[2];
    const float* W1      = (const float*)d_in[3];
    const float* b1      = (const float*)d_in[4];
    const float* W2      = (const float*)d_in[5];
    const float* b2      = (const float*)d_in[6];
    float* out = (float*)d_out;

    pack_w1_kernel<<<64, 256>>>(W1);
    cudaFuncSetAttribute(dat_mma2_kernel, cudaFuncAttributeMaxDynamicSharedMemorySize, SMEM_TOTAL);
    dat_mma2_kernel<<<CTAS, THREADS, SMEM_TOTAL>>>(sampled, valid, y_norm, W1, b1, W2, b2, out);
}

// round 8
// speedup vs baseline: 4.0094x; 1.3492x over previous
#include <cuda_runtime.h>
#include <cuda_fp16.h>
#include <cstdint>

// DepthAwareTokenAggregator via mma.sync fp16 (sm_80 ISA).
// B=8, N=512, Y=64, C=256. 2 tokens/CTA: M=128, K=256, N=256 (2 passes of 128).
// W1 prepacked to fp16 once by a pre-kernel; streamed via cp.async.
// Single fp16 product (A_fp16 * W1_fp16, fp32 accum): GEMM err only perturbs
// softmax logits; output built from exact fp32 sampled -> rel err ~1e-4.

#define Yd 64
#define Cd 256
#define THREADS 256
#define CTAS 2048

// ---- smem byte offsets ----
#define SM_YN    0        // 64 f32
#define SM_B1    256      // 256 f32
#define SM_W2    1280     // 256 f32
#define SM_W1L   2304     // 256 f32 (W1 row 256: y_norm feature row)
#define SM_LP    3328     // 4 x 128 f32 logit partials
#define SM_LOG   5376     // 128 f32
#define SM_WGT   5888     // 128 f32
#define SM_A     6400     // 128 rows x 264 fp16 (stride 528B) = 67584
#define SM_B     73984    // 2 bufs x 18432 (128 n x 72 k fp16, stride 144B)
#define SMEM_TOTAL 110848

#define A_STRIDE 528
#define B_STRIDE 144      // 64 fp16 (128B) + 16B pad
#define BCHUNK   18432

// prepacked W1 fp16: [2 pass][4 chunk][128 n][64 k]
__device__ __half w1pack[2 * 4 * 128 * 64];

static __device__ __forceinline__ uint32_t smem_u32(const void* p) {
    uint32_t a;
    asm("{ .reg .u64 t; cvta.to.shared.u64 t, %1; cvt.u32.u64 %0, t; }" : "=r"(a) : "l"(p));
    return a;
}

static __device__ __forceinline__ void ldsm4(uint32_t* r, uint32_t addr) {
    asm volatile("ldmatrix.sync.aligned.m8n8.x4.shared.b16 {%0,%1,%2,%3}, [%4];"
                 : "=r"(r[0]), "=r"(r[1]), "=r"(r[2]), "=r"(r[3]) : "r"(addr));
}

static __device__ __forceinline__ void mma16816(float* d, const uint32_t* a,
                                                uint32_t b0, uint32_t b1) {
    asm volatile(
        "mma.sync.aligned.m16n8k16.row.col.f32.f16.f16.f32 "
        "{%0,%1,%2,%3}, {%4,%5,%6,%7}, {%8,%9}, {%0,%1,%2,%3};"
        : "+f"(d[0]), "+f"(d[1]), "+f"(d[2]), "+f"(d[3])
        : "r"(a[0]), "r"(a[1]), "r"(a[2]), "r"(a[3]), "r"(b0), "r"(b1));
}

#define CP_ASYNC16(dst, src) \
    asm volatile("cp.async.cg.shared.global [%0], [%1], 16;" :: "r"(dst), "l"(src) : "memory")
#define CP_COMMIT() asm volatile("cp.async.commit_group;" ::: "memory")
#define CP_WAIT1()  asm volatile("cp.async.wait_group 1;" ::: "memory")
#define CP_WAIT0()  asm volatile("cp.async.wait_group 0;" ::: "memory")

static __device__ __forceinline__ float gelu_exact(float x) {
    return 0.5f * x * (1.0f + erff(x * 0.70710678118654752440f));
}

// ---- pre-kernel: pack W1 (f32 [257,256]) -> fp16 chunk blocks ----
__global__ void pack_w1_kernel(const float* __restrict__ W1) {
    int gid = blockIdx.x * blockDim.x + threadIdx.x;   // 0..16383
    #pragma unroll
    for (int it = 0; it < 4; it++) {
        int e = gid + it * 16384;                      // 0..65535
        int p = e >> 15;
        int rem = e & 32767;
        int k = rem >> 7;                              // 0..255
        int n = rem & 127;
        int c = k >> 6, kk = k & 63;
        float x = W1[(size_t)k * Cd + p * 128 + n];
        w1pack[(size_t)(p * 4 + c) * 8192 + n * 64 + kk] = __float2half_rn(x);
    }
}

static __device__ __forceinline__ void issue_chunk(uint32_t sbase, int tid, int i) {
    const uint32_t dstb = sbase + SM_B + (i & 1) * BCHUNK;
    const __half* srcb = w1pack + (size_t)i * 8192;
    #pragma unroll
    for (int j = 0; j < 4; j++) {
        int idx16 = tid * 4 + j;                       // 0..1023
        int n = idx16 >> 3, ko = idx16 & 7;
        uint32_t dst = dstb + n * B_STRIDE + ko * 16;
        const void* src = srcb + idx16 * 8;
        CP_ASYNC16(dst, src);
    }
}

static __device__ __forceinline__ void epilogue_pass(
    float acc[4][4][4], float* lp, int p, const char* smem, int lane, int m0, int n0w)
{
    const float* b1s  = (const float*)(smem + SM_B1);
    const float* w2s  = (const float*)(smem + SM_W2);
    const float* w1ls = (const float*)(smem + SM_W1L);
    const float* yns  = (const float*)(smem + SM_YN);
    float yl[8], bb[8], ww[8];
    #pragma unroll
    for (int nt = 0; nt < 4; nt++)
        #pragma unroll
        for (int eb = 0; eb < 2; eb++) {
            int n = p * 128 + n0w + nt * 8 + 2 * (lane & 3) + eb;
            yl[nt * 2 + eb] = w1ls[n];
            bb[nt * 2 + eb] = b1s[n];
            ww[nt * 2 + eb] = w2s[n];
        }
    #pragma unroll
    for (int mt = 0; mt < 4; mt++)
        #pragma unroll
        for (int h = 0; h < 2; h++) {
            int row = m0 + mt * 16 + h * 8 + (lane >> 2);
            float yn = yns[row & 63];
            float s = 0.f;
            #pragma unroll
            for (int nt = 0; nt < 4; nt++)
                #pragma unroll
                for (int eb = 0; eb < 2; eb++) {
                    float x = acc[mt][nt][h * 2 + eb] + yn * yl[nt * 2 + eb] + bb[nt * 2 + eb];
                    s += gelu_exact(x) * ww[nt * 2 + eb];
                }
            lp[mt * 2 + h] += s;
        }
}

__global__ __launch_bounds__(THREADS, 2)
void dat_mma3_kernel(const float* __restrict__ sampled,
                     const float* __restrict__ valid,
                     const float* __restrict__ y_norm,
                     const float* __restrict__ W1,
                     const float* __restrict__ b1,
                     const float* __restrict__ W2,
                     const float* __restrict__ b2,
                     float* __restrict__ out)
{
    extern __shared__ char smem[];
    const uint32_t sbase = smem_u32(smem);
    const int tid  = threadIdx.x;
    const int wid  = tid >> 5;
    const int lane = tid & 31;
    const int bn2  = blockIdx.x;

    // warp tile: wm in {0,1} -> 64 m-rows, wn in {0..3} -> 32 n-cols
    const int wm = wid & 1, wn = wid >> 1;
    const int m0 = wm * 64, n0w = wn * 32;

    // B pipeline first so cp.async overlaps the A load/convert
    issue_chunk(sbase, tid, 0); CP_COMMIT();
    issue_chunk(sbase, tid, 1); CP_COMMIT();

    // small vectors
    if (tid < Yd) ((float*)(smem + SM_YN))[tid] = y_norm[tid];
    ((float*)(smem + SM_B1))[tid]  = b1[tid];
    ((float*)(smem + SM_W2))[tid]  = W2[tid];
    ((float*)(smem + SM_W1L))[tid] = W1[(size_t)Cd * Cd + tid];

    // ---- A: 128 rows x 256 f32 -> fp16, padded row-major ----
    {
        const float4* src = (const float4*)(sampled + (size_t)bn2 * (2 * Yd * Cd));
        #pragma unroll
        for (int i = 0; i < 32; i++) {
            int idx4 = tid + i * THREADS;          // 0..8191
            float4 v = src[idx4];
            int row = idx4 >> 6;
            int c4  = (idx4 & 63) << 2;
            __half2 h01 = __floats2half2_rn(v.x, v.y);
            __half2 h23 = __floats2half2_rn(v.z, v.w);
            uint32_t byo = row * A_STRIDE + c4 * 2;
            *(uint2*)(smem + SM_A + byo) =
                make_uint2(*(uint32_t*)&h01, *(uint32_t*)&h23);
        }
    }

    float acc[4][4][4];
    #pragma unroll
    for (int mt = 0; mt < 4; mt++)
        #pragma unroll
        for (int nt = 0; nt < 4; nt++)
            #pragma unroll
            for (int e = 0; e < 4; e++) acc[mt][nt][e] = 0.f;
    float lp[8] = {0.f, 0.f, 0.f, 0.f, 0.f, 0.f, 0.f, 0.f};

    // ---- main loop: 8 chunks (pass = i>>2, k-chunk = i&3, 64 k each) ----
    #pragma unroll 1
    for (int i = 0; i < 8; i++) {
        if (i < 7) { CP_WAIT1(); } else { CP_WAIT0(); }
        __syncthreads();

        const uint32_t buf = sbase + SM_B + (i & 1) * BCHUNK;
        const int kbase = (i & 3) * 64;

        #pragma unroll
        for (int kk = 0; kk < 4; kk++) {
            const int kglob = kbase + kk * 16;
            uint32_t a_[4][4];
            #pragma unroll
            for (int mt = 0; mt < 4; mt++) {
                uint32_t aaddr = sbase + SM_A
                    + (uint32_t)((m0 + mt * 16 + (lane & 15)) * A_STRIDE
                                 + (kglob + ((lane & 16) >> 1)) * 2);
                ldsm4(a_[mt], aaddr);
            }
            const uint32_t bbase =
                (uint32_t)((n0w + (lane & 7) + ((lane & 16) >> 1)) * B_STRIDE
                           + (kk * 16 + (lane & 8)) * 2);
            uint32_t bf[2][4];
            ldsm4(bf[0], buf + bbase);
            ldsm4(bf[1], buf + bbase + 16 * B_STRIDE);
            #pragma unroll
            for (int mt = 0; mt < 4; mt++)
                #pragma unroll
                for (int q = 0; q < 2; q++)
                    #pragma unroll
                    for (int h = 0; h < 2; h++)
                        mma16816(acc[mt][q * 2 + h], a_[mt], bf[q][2 * h], bf[q][2 * h + 1]);
        }

        if (i == 3) {
            epilogue_pass(acc, lp, 0, smem, lane, m0, n0w);
            #pragma unroll
            for (int mt = 0; mt < 4; mt++)
                #pragma unroll
                for (int nt = 0; nt < 4; nt++)
                    #pragma unroll
                    for (int e = 0; e < 4; e++) acc[mt][nt][e] = 0.f;
        }
        __syncthreads();
        if (i + 2 < 8) { issue_chunk(sbase, tid, i + 2); CP_COMMIT(); }
    }
    epilogue_pass(acc, lp, 1, smem, lane, m0, n0w);

    // ---- reduce logits across the 4 lanes sharing a row, write per-wn partials ----
    #pragma unroll
    for (int i = 0; i < 8; i++) {
        lp[i] += __shfl_xor_sync(0xffffffffu, lp[i], 1);
        lp[i] += __shfl_xor_sync(0xffffffffu, lp[i], 2);
    }
    if ((lane & 3) == 0) {
        #pragma unroll
        for (int mt = 0; mt < 4; mt++)
            #pragma unroll
            for (int h = 0; h < 2; h++) {
                int row = m0 + mt * 16 + h * 8 + (lane >> 2);
                ((float*)(smem + SM_LP))[wn * 128 + row] = lp[mt * 2 + h];
            }
    }
    __syncthreads();

    if (tid < 128) {
        const float* lps = (const float*)(smem + SM_LP);
        ((float*)(smem + SM_LOG))[tid] =
            lps[tid] + lps[128 + tid] + lps[256 + tid] + lps[384 + tid] + __ldg(b2);
    }
    __syncthreads();

    // ---- masked softmax: warp 0 -> token 0, warp 1 -> token 1 ----
    if (wid < 2) {
        const int tk = wid;
        const float* logit = (const float*)(smem + SM_LOG);
        const float v0 = valid[(size_t)(bn2 * 2 + tk) * Yd + lane];
        const float v1 = valid[(size_t)(bn2 * 2 + tk) * Yd + lane + 32];
        float l0 = (v0 < 0.5f) ? -10000.0f : logit[tk * 64 + lane];
        float l1 = (v1 < 0.5f) ? -10000.0f : logit[tk * 64 + lane + 32];

        float m = fmaxf(l0, l1);
        #pragma unroll
        for (int off = 16; off > 0; off >>= 1)
            m = fmaxf(m, __shfl_xor_sync(0xffffffffu, m, off));
        float e0 = expf(l0 - m), e1 = expf(l1 - m);
        float s = e0 + e1;
        #pragma unroll
        for (int off = 16; off > 0; off >>= 1)
            s += __shfl_xor_sync(0xffffffffu, s, off);
        float p0 = (e0 / s) * v0;
        float p1 = (e1 / s) * v1;
        float s2 = p0 + p1;
        #pragma unroll
        for (int off = 16; off > 0; off >>= 1)
            s2 += __shfl_xor_sync(0xffffffffu, s2, off);
        const float inv = 1.0f / fmaxf(s2, 1e-6f);
        ((float*)(smem + SM_WGT))[tk * 64 + lane]      = p0 * inv;
        ((float*)(smem + SM_WGT))[tk * 64 + lane + 32] = p1 * inv;
    }
    __syncthreads();

    // ---- aggregation: re-read sampled f32 (L2-hot) for full output precision ----
    {
        const float* wgt = (const float*)(smem + SM_WGT);
        const int c = tid;
        #pragma unroll
        for (int t = 0; t < 2; t++) {
            const float* sp = sampled + ((size_t)(bn2 * 2 + t) * Yd) * Cd + c;
            float o = 0.f;
            #pragma unroll 8
            for (int y = 0; y < Yd; y++)
                o = fmaf(wgt[t * 64 + y], sp[(size_t)y * Cd], o);
            out[(size_t)(bn2 * 2 + t) * Cd + c] = o;
        }
    }
}

extern "C" void kernel_launch(void* const* d_in, const int* in_sizes, int n_in,
                              void* d_out, int out_size)
{
    const float* sampled = (const float*)d_in[0];
    const float* valid   = (const float*)d_in[1];
    const float* y_norm  = (const float*)d_in[2];
    const float* W1      = (const float*)d_in[3];
    const float* b1      = (const float*)d_in[4];
    const float* W2      = (const float*)d_in[5];
    const float* b2      = (const float*)d_in[6];
    float* out = (float*)d_out;

    pack_w1_kernel<<<64, 256>>>(W1);
    cudaFuncSetAttribute(dat_mma3_kernel, cudaFuncAttributeMaxDynamicSharedMemorySize, SMEM_TOTAL);
    dat_mma3_kernel<<<CTAS, THREADS, SMEM_TOTAL>>>(sampled, valid, y_norm, W1, b1, W2, b2, out);
}

// round 9
// speedup vs baseline: 4.4398x; 1.1073x over previous
#include <cuda_runtime.h>
#include <cuda_fp16.h>
#include <cstdint>

// DepthAwareTokenAggregator via mma.sync fp16 (sm_80 ISA).
// B=8, N=512, Y=64, C=256. 2 tokens/CTA: M=128, K=256, N=256 (2 passes of 128).
// 512 threads (16 warps, 32x32 warp tile) for 2 CTAs/SM = 32 warps/SM.
// W1 prepacked to fp16 once; streamed via cp.async double-buffer.

#define Yd 64
#define Cd 256
#define THREADS 512
#define CTAS 2048

// ---- smem byte offsets ----
#define SM_YN    0        // 64 f32
#define SM_B1    256      // 256 f32
#define SM_W2    1280     // 256 f32
#define SM_W1L   2304     // 256 f32 (W1 row 256: y_norm feature row)
#define SM_LP    3328     // 4 x 128 f32 logit partials
#define SM_LOG   5376     // 128 f32
#define SM_WGT   5888     // 128 f32
#define SM_A     6400     // 128 rows x 264 fp16 (stride 528B) = 67584
#define SM_B     73984    // 2 bufs x 18432 (128 n x 72 k fp16, stride 144B)
#define SMEM_TOTAL 110848

#define A_STRIDE 528
#define B_STRIDE 144      // 64 fp16 (128B) + 16B pad
#define BCHUNK   18432

// prepacked W1 fp16: [2 pass][4 chunk][128 n][64 k]
__device__ __half w1pack[2 * 4 * 128 * 64];

static __device__ __forceinline__ uint32_t smem_u32(const void* p) {
    uint32_t a;
    asm("{ .reg .u64 t; cvta.to.shared.u64 t, %1; cvt.u32.u64 %0, t; }" : "=r"(a) : "l"(p));
    return a;
}

static __device__ __forceinline__ void ldsm4(uint32_t* r, uint32_t addr) {
    asm volatile("ldmatrix.sync.aligned.m8n8.x4.shared.b16 {%0,%1,%2,%3}, [%4];"
                 : "=r"(r[0]), "=r"(r[1]), "=r"(r[2]), "=r"(r[3]) : "r"(addr));
}

static __device__ __forceinline__ void mma16816(float* d, const uint32_t* a,
                                                uint32_t b0, uint32_t b1) {
    asm volatile(
        "mma.sync.aligned.m16n8k16.row.col.f32.f16.f16.f32 "
        "{%0,%1,%2,%3}, {%4,%5,%6,%7}, {%8,%9}, {%0,%1,%2,%3};"
        : "+f"(d[0]), "+f"(d[1]), "+f"(d[2]), "+f"(d[3])
        : "r"(a[0]), "r"(a[1]), "r"(a[2]), "r"(a[3]), "r"(b0), "r"(b1));
}

#define CP_ASYNC16(dst, src) \
    asm volatile("cp.async.cg.shared.global [%0], [%1], 16;" :: "r"(dst), "l"(src) : "memory")
#define CP_COMMIT() asm volatile("cp.async.commit_group;" ::: "memory")
#define CP_WAIT1()  asm volatile("cp.async.wait_group 1;" ::: "memory")
#define CP_WAIT0()  asm volatile("cp.async.wait_group 0;" ::: "memory")

static __device__ __forceinline__ float gelu_exact(float x) {
    return 0.5f * x * (1.0f + erff(x * 0.70710678118654752440f));
}

// ---- pre-kernel: pack W1 (f32 [257,256]) -> fp16 chunk blocks ----
__global__ void pack_w1_kernel(const float* __restrict__ W1) {
    int gid = blockIdx.x * blockDim.x + threadIdx.x;   // 0..16383
    #pragma unroll
    for (int it = 0; it < 4; it++) {
        int e = gid + it * 16384;                      // 0..65535
        int p = e >> 15;
        int rem = e & 32767;
        int k = rem >> 7;                              // 0..255
        int n = rem & 127;
        int c = k >> 6, kk = k & 63;
        float x = W1[(size_t)k * Cd + p * 128 + n];
        w1pack[(size_t)(p * 4 + c) * 8192 + n * 64 + kk] = __float2half_rn(x);
    }
}

static __device__ __forceinline__ void issue_chunk(uint32_t sbase, int tid, int i) {
    const uint32_t dstb = sbase + SM_B + (i & 1) * BCHUNK;
    const __half* srcb = w1pack + (size_t)i * 8192;
    #pragma unroll
    for (int j = 0; j < 2; j++) {
        int idx16 = tid * 2 + j;                       // 0..1023
        int n = idx16 >> 3, ko = idx16 & 7;
        uint32_t dst = dstb + n * B_STRIDE + ko * 16;
        const void* src = srcb + idx16 * 8;
        CP_ASYNC16(dst, src);
    }
}

static __device__ __forceinline__ void epilogue_pass(
    float acc[2][4][4], float* lp, int p, const char* smem, int lane, int m0, int n0w)
{
    const float* b1s  = (const float*)(smem + SM_B1);
    const float* w2s  = (const float*)(smem + SM_W2);
    const float* w1ls = (const float*)(smem + SM_W1L);
    const float* yns  = (const float*)(smem + SM_YN);
    float yl[8], bb[8], ww[8];
    #pragma unroll
    for (int nt = 0; nt < 4; nt++)
        #pragma unroll
        for (int eb = 0; eb < 2; eb++) {
            int n = p * 128 + n0w + nt * 8 + 2 * (lane & 3) + eb;
            yl[nt * 2 + eb] = w1ls[n];
            bb[nt * 2 + eb] = b1s[n];
            ww[nt * 2 + eb] = w2s[n];
        }
    #pragma unroll
    for (int mt = 0; mt < 2; mt++)
        #pragma unroll
        for (int h = 0; h < 2; h++) {
            int row = m0 + mt * 16 + h * 8 + (lane >> 2);
            float yn = yns[row & 63];
            float s = 0.f;
            #pragma unroll
            for (int nt = 0; nt < 4; nt++)
                #pragma unroll
                for (int eb = 0; eb < 2; eb++) {
                    float x = acc[mt][nt][h * 2 + eb] + yn * yl[nt * 2 + eb] + bb[nt * 2 + eb];
                    s += gelu_exact(x) * ww[nt * 2 + eb];
                }
            lp[mt * 2 + h] += s;
        }
}

__global__ __launch_bounds__(THREADS, 2)
void dat_mma4_kernel(const float* __restrict__ sampled,
                     const float* __restrict__ valid,
                     const float* __restrict__ y_norm,
                     const float* __restrict__ W1,
                     const float* __restrict__ b1,
                     const float* __restrict__ W2,
                     const float* __restrict__ b2,
                     float* __restrict__ out)
{
    extern __shared__ char smem[];
    const uint32_t sbase = smem_u32(smem);
    const int tid  = threadIdx.x;
    const int wid  = tid >> 5;
    const int lane = tid & 31;
    const int bn2  = blockIdx.x;

    // warp tile: wm in {0..3} -> 32 m-rows, wn in {0..3} -> 32 n-cols
    const int wm = wid & 3, wn = wid >> 2;
    const int m0 = wm * 32, n0w = wn * 32;

    // B pipeline first so cp.async overlaps the A load/convert
    issue_chunk(sbase, tid, 0); CP_COMMIT();
    issue_chunk(sbase, tid, 1); CP_COMMIT();

    // small vectors
    if (tid < Yd) ((float*)(smem + SM_YN))[tid] = y_norm[tid];
    if (tid < Cd) {
        ((float*)(smem + SM_B1))[tid]  = b1[tid];
        ((float*)(smem + SM_W2))[tid]  = W2[tid];
        ((float*)(smem + SM_W1L))[tid] = W1[(size_t)Cd * Cd + tid];
    }

    // ---- A: 128 rows x 256 f32 -> fp16, padded row-major; affine pointers ----
    {
        const float4* src = (const float4*)(sampled + (size_t)bn2 * (2 * Yd * Cd)) + tid;
        char* dst = smem + SM_A + (tid >> 6) * A_STRIDE + (tid & 63) * 8;
        #pragma unroll
        for (int i = 0; i < 16; i++) {
            float4 v = *src;
            __half2 h01 = __floats2half2_rn(v.x, v.y);
            __half2 h23 = __floats2half2_rn(v.z, v.w);
            *(uint2*)dst = make_uint2(*(uint32_t*)&h01, *(uint32_t*)&h23);
            src += THREADS;
            dst += 8 * A_STRIDE;   // 512 threads cover 8 rows per step
        }
    }

    float acc[2][4][4];
    #pragma unroll
    for (int mt = 0; mt < 2; mt++)
        #pragma unroll
        for (int nt = 0; nt < 4; nt++)
            #pragma unroll
            for (int e = 0; e < 4; e++) acc[mt][nt][e] = 0.f;
    float lp[4] = {0.f, 0.f, 0.f, 0.f};

    // hoisted smem bases
    const uint32_t abase = sbase + SM_A
        + (uint32_t)((m0 + (lane & 15)) * A_STRIDE + ((lane & 16) >> 1) * 2);
    const uint32_t blane = (uint32_t)((n0w + (lane & 7) + ((lane & 16) >> 1)) * B_STRIDE
                                      + (lane & 8) * 2);

    // ---- main loop: 8 chunks (pass = i>>2, k-chunk = i&3, 64 k each) ----
    #pragma unroll
    for (int i = 0; i < 8; i++) {
        if (i < 7) { CP_WAIT1(); } else { CP_WAIT0(); }
        __syncthreads();

        const uint32_t buf = sbase + SM_B + (i & 1) * BCHUNK + blane;
        const int kbase = (i & 3) * 64;

        #pragma unroll
        for (int kk = 0; kk < 4; kk++) {
            const int kglob = kbase + kk * 16;
            uint32_t a_[2][4];
            ldsm4(a_[0], abase + kglob * 2);
            ldsm4(a_[1], abase + kglob * 2 + 16 * A_STRIDE);
            uint32_t bf[2][4];
            ldsm4(bf[0], buf + kk * 32);
            ldsm4(bf[1], buf + kk * 32 + 16 * B_STRIDE);
            #pragma unroll
            for (int mt = 0; mt < 2; mt++)
                #pragma unroll
                for (int q = 0; q < 2; q++)
                    #pragma unroll
                    for (int h = 0; h < 2; h++)
                        mma16816(acc[mt][q * 2 + h], a_[mt], bf[q][2 * h], bf[q][2 * h + 1]);
        }

        if (i == 3) {
            epilogue_pass(acc, lp, 0, smem, lane, m0, n0w);
            #pragma unroll
            for (int mt = 0; mt < 2; mt++)
                #pragma unroll
                for (int nt = 0; nt < 4; nt++)
                    #pragma unroll
                    for (int e = 0; e < 4; e++) acc[mt][nt][e] = 0.f;
        }
        __syncthreads();
        if (i + 2 < 8) { issue_chunk(sbase, tid, i + 2); CP_COMMIT(); }
    }
    epilogue_pass(acc, lp, 1, smem, lane, m0, n0w);

    // ---- reduce logits across the 4 lanes sharing a row, write per-wn partials ----
    #pragma unroll
    for (int i = 0; i < 4; i++) {
        lp[i] += __shfl_xor_sync(0xffffffffu, lp[i], 1);
        lp[i] += __shfl_xor_sync(0xffffffffu, lp[i], 2);
    }
    if ((lane & 3) == 0) {
        #pragma unroll
        for (int mt = 0; mt < 2; mt++)
            #pragma unroll
            for (int h = 0; h < 2; h++) {
                int row = m0 + mt * 16 + h * 8 + (lane >> 2);
                ((float*)(smem + SM_LP))[wn * 128 + row] = lp[mt * 2 + h];
            }
    }
    __syncthreads();

    if (tid < 128) {
        const float* lps = (const float*)(smem + SM_LP);
        ((float*)(smem + SM_LOG))[tid] =
            lps[tid] + lps[128 + tid] + lps[256 + tid] + lps[384 + tid] + __ldg(b2);
    }
    __syncthreads();

    // ---- masked softmax: warp 0 -> token 0, warp 1 -> token 1 ----
    if (wid < 2) {
        const int tk = wid;
        const float* logit = (const float*)(smem + SM_LOG);
        const float v0 = valid[(size_t)(bn2 * 2 + tk) * Yd + lane];
        const float v1 = valid[(size_t)(bn2 * 2 + tk) * Yd + lane + 32];
        float l0 = (v0 < 0.5f) ? -10000.0f : logit[tk * 64 + lane];
        float l1 = (v1 < 0.5f) ? -10000.0f : logit[tk * 64 + lane + 32];

        float m = fmaxf(l0, l1);
        #pragma unroll
        for (int off = 16; off > 0; off >>= 1)
            m = fmaxf(m, __shfl_xor_sync(0xffffffffu, m, off));
        float e0 = expf(l0 - m), e1 = expf(l1 - m);
        float s = e0 + e1;
        #pragma unroll
        for (int off = 16; off > 0; off >>= 1)
            s += __shfl_xor_sync(0xffffffffu, s, off);
        float p0 = (e0 / s) * v0;
        float p1 = (e1 / s) * v1;
        float s2 = p0 + p1;
        #pragma unroll
        for (int off = 16; off > 0; off >>= 1)
            s2 += __shfl_xor_sync(0xffffffffu, s2, off);
        const float inv = 1.0f / fmaxf(s2, 1e-6f);
        ((float*)(smem + SM_WGT))[tk * 64 + lane]      = p0 * inv;
        ((float*)(smem + SM_WGT))[tk * 64 + lane + 32] = p1 * inv;
    }
    __syncthreads();

    // ---- aggregation: one output element per thread; re-read sampled f32 (L2-hot) ----
    {
        const float* wgt = (const float*)(smem + SM_WGT) + (tid >> 8) * 64;
        const int t = tid >> 8, c = tid & 255;
        const float* sp = sampled + ((size_t)(bn2 * 2 + t) * Yd) * Cd + c;
        float o = 0.f;
        #pragma unroll 8
        for (int y = 0; y < Yd; y++)
            o = fmaf(wgt[y], sp[(size_t)y * Cd], o);
        out[(size_t)(bn2 * 2 + t) * Cd + c] = o;
    }
}

extern "C" void kernel_launch(void* const* d_in, const int* in_sizes, int n_in,
                              void* d_out, int out_size)
{
    const float* sampled = (const float*)d_in[0];
    const float* valid   = (const float*)d_in[1];
    const float* y_norm  = (const float*)d_in[2];
    const float* W1      = (const float*)d_in[3];
    const float* b1      = (const float*)d_in[4];
    const float* W2      = (const float*)d_in[5];
    const float* b2      = (const float*)d_in[6];
    float* out = (float*)d_out;

    pack_w1_kernel<<<64, 256>>>(W1);
    cudaFuncSetAttribute(dat_mma4_kernel, cudaFuncAttributeMaxDynamicSharedMemorySize, SMEM_TOTAL);
    dat_mma4_kernel<<<CTAS, THREADS, SMEM_TOTAL>>>(sampled, valid, y_norm, W1, b1, W2, b2, out);
}